// round 1
// baseline (speedup 1.0000x reference)
#include <cuda_runtime.h>
#include <math.h>

#define B_    1024
#define C1    22
#define T1    438
#define C2    20
#define T2    439
#define DOUT  18
#define TPAD  452
#define N1F   448512.0f
#define N2F   449536.0f
#define LOG_RECT_EPS (-9.210340371976184f)
#define NSWEEP 9

// ---------------- scratch (device globals: allocation-free) ----------------
__device__ float g_h1[B_*C1*T1];            // conv1 output (pre-bn1)
__device__ float g_sig[B_*C2*T2];           // conv2 output (pre-bn2)
__device__ float g_stats1[2*C1];            // sum / sumsq per channel
__device__ float g_stats2[2*C2];
__device__ float g_logQ[B_*3*DOUT*DOUT];
__device__ float g_logK[B_*3*DOUT*DOUT];
__device__ float g_logV[B_*3*DOUT*DOUT];

// ---------------- utility kernels ----------------
__global__ void zero_stats() {
    int t = threadIdx.x;
    if (t < 2*C1) g_stats1[t] = 0.f;
    if (t < 2*C2) g_stats2[t] = 0.f;
}

// ---------------- K1: conv1 (22x22 pointwise) + bn1 statistics ----------------
__global__ __launch_bounds__(256) void k1(const float* __restrict__ x,
                                          const float* __restrict__ w1,
                                          const float* __restrict__ b1) {
    int b = blockIdx.x, tid = threadIdx.x;
    __shared__ float sW[C1*C1];
    __shared__ float sb[C1];
    __shared__ float red[8][2*C1];
    for (int i = tid; i < C1*C1; i += 256) sW[i] = w1[i];
    if (tid < C1) sb[tid] = b1[tid];
    __syncthreads();

    float as[C1], aq[C1];
#pragma unroll
    for (int o = 0; o < C1; ++o) { as[o] = 0.f; aq[o] = 0.f; }

    for (int t = tid; t < T1; t += 256) {
        float xv[C1];
#pragma unroll
        for (int h = 0; h < C1; ++h) xv[h] = x[(b*C1 + h)*T1 + t];
#pragma unroll
        for (int o = 0; o < C1; ++o) {
            float v = sb[o];
#pragma unroll
            for (int h = 0; h < C1; ++h) v += sW[o*C1 + h] * xv[h];
            g_h1[(b*C1 + o)*T1 + t] = v;
            as[o] += v; aq[o] += v*v;
        }
    }
#pragma unroll
    for (int o = 0; o < C1; ++o) {
#pragma unroll
        for (int off = 16; off; off >>= 1) {
            as[o] += __shfl_xor_sync(0xffffffffu, as[o], off);
            aq[o] += __shfl_xor_sync(0xffffffffu, aq[o], off);
        }
    }
    int wid = tid >> 5, lane = tid & 31;
    if (lane == 0) {
#pragma unroll
        for (int o = 0; o < C1; ++o) { red[wid][o] = as[o]; red[wid][C1+o] = aq[o]; }
    }
    __syncthreads();
    if (tid < 2*C1) {
        float s = 0.f;
#pragma unroll
        for (int w = 0; w < 8; ++w) s += red[w][tid];
        atomicAdd(&g_stats1[tid], s);
    }
}

// ---------------- K3: bn1 + conv2 (12-tap, pad 6) -> g_sig (pre-bn2) ----------------
__global__ __launch_bounds__(256) void k3(const float* __restrict__ w2,
                                          const float* __restrict__ b2,
                                          const float* __restrict__ g1,
                                          const float* __restrict__ be1) {
    extern __shared__ float sm[];
    float* sIn = sm;                 // C1*TPAD  (bn1'd, zero-padded by 6+pad)
    float* sw  = sm + C1*TPAD;       // 20*22*12 weights
    __shared__ float sc[C1], sh[C1], sb2[C2];
    int b = blockIdx.x, tid = threadIdx.x;

    if (tid < C1) {
        float m = g_stats1[tid] / N1F;
        float v = g_stats1[C1+tid] / N1F - m*m;
        float s = rsqrtf(v + 1e-5f) * g1[tid];
        sc[tid] = s; sh[tid] = be1[tid] - m*s;
    }
    if (tid < C2) sb2[tid] = b2[tid];
    for (int i = tid; i < C2*C1*12; i += 256) sw[i] = w2[i];
    __syncthreads();

    for (int e = tid; e < C1*TPAD; e += 256) {
        int c = e / TPAD, tt = e % TPAD, t = tt - 6;
        float v = 0.f;
        if ((unsigned)t < (unsigned)T1) v = g_h1[(b*C1 + c)*T1 + t]*sc[c] + sh[c];
        sIn[e] = v;
    }
    __syncthreads();

    // units: (o, block of 8 output positions); 20 * 55 = 1100
    for (int u = tid; u < C2*55; u += 256) {
        int o = u / 55, tb = u % 55, tp0 = tb*8;
        float acc[8];
#pragma unroll
        for (int j = 0; j < 8; ++j) acc[j] = sb2[o];
        const float* wrow = sw + o*(C1*12);
#pragma unroll 1
        for (int i = 0; i < C1; ++i) {
            float win[19];
            const float* inr = sIn + i*TPAD + tp0;
#pragma unroll
            for (int j = 0; j < 19; ++j) win[j] = inr[j];
#pragma unroll
            for (int k = 0; k < 12; ++k) {
                float wv = wrow[i*12 + k];
#pragma unroll
                for (int j = 0; j < 8; ++j) acc[j] += wv * win[k+j];
            }
        }
#pragma unroll
        for (int j = 0; j < 8; ++j) {
            int tp = tp0 + j;
            if (tp < T2) g_sig[(b*C2 + o)*T2 + tp] = acc[j];
        }
    }
}

// ---------------- K3b: bn2 statistics ----------------
__global__ __launch_bounds__(256) void k3b() {
    int b = blockIdx.x, tid = threadIdx.x;
    int w = tid >> 5, lane = tid & 31;
    for (int o = w; o < C2; o += 8) {
        float s = 0.f, q = 0.f;
        for (int t = lane; t < T2; t += 32) {
            float v = g_sig[(b*C2 + o)*T2 + t];
            s += v; q += v*v;
        }
#pragma unroll
        for (int off = 16; off; off >>= 1) {
            s += __shfl_xor_sync(0xffffffffu, s, off);
            q += __shfl_xor_sync(0xffffffffu, q, off);
        }
        if (lane == 0) { atomicAdd(&g_stats2[o], s); atomicAdd(&g_stats2[C2+o], q); }
    }
}

// ---------------- parallel-order Jacobi eigensolver (18x18, one warp) ----------------
__device__ __forceinline__ void build_schedule(unsigned char* pp, unsigned char* pq) {
    int a[18];
    for (int i = 0; i < 18; ++i) a[i] = i;
    for (int r = 0; r < 17; ++r) {
        for (int k = 0; k < 9; ++k) {
            int x = a[k], y = a[17-k];
            pp[r*9 + k] = (unsigned char)(x < y ? x : y);
            pq[r*9 + k] = (unsigned char)(x < y ? y : x);
        }
        int last = a[17];
        for (int i = 17; i >= 2; --i) a[i] = a[i-1];
        a[1] = last;
    }
}

// A, V: 18x18 stored with row stride 19 in shared memory.
__device__ __forceinline__ void jacobi18(float* A, float* V, float* cb, float* sb,
                                         const unsigned char* pp, const unsigned char* pq,
                                         int lane) {
    for (int e = lane; e < 18*18; e += 32) {
        int i = e/18, j = e%18;
        V[i*19 + j] = (i == j) ? 1.f : 0.f;
    }
    __syncwarp();
    for (int sweep = 0; sweep < NSWEEP; ++sweep) {
        for (int r = 0; r < 17; ++r) {
            const unsigned char* rp = pp + r*9;
            const unsigned char* rq = pq + r*9;
            if (lane < 9) {
                int p = rp[lane], q = rq[lane];
                float apq = A[p*19 + q];
                float c = 1.f, s = 0.f;
                if (fabsf(apq) > 1e-35f) {
                    float theta = 0.5f*(A[q*19+q] - A[p*19+p]) / apq;
                    float t = 1.f/(fabsf(theta) + sqrtf(theta*theta + 1.f));
                    t = (theta < 0.f) ? -t : t;
                    c = rsqrtf(t*t + 1.f);
                    s = t*c;
                }
                cb[lane] = c; sb[lane] = s;
            }
            __syncwarp();
            if (lane < 18) {                       // column update (A * J) + V * J
                int k = lane;
                for (int m2 = 0; m2 < 9; ++m2) {
                    int p = rp[m2], q = rq[m2];
                    float c = cb[m2], s = sb[m2];
                    float akp = A[k*19+p], akq = A[k*19+q];
                    A[k*19+p] = c*akp - s*akq;
                    A[k*19+q] = s*akp + c*akq;
                    float vkp = V[k*19+p], vkq = V[k*19+q];
                    V[k*19+p] = c*vkp - s*vkq;
                    V[k*19+q] = s*vkp + c*vkq;
                }
            }
            __syncwarp();
            if (lane < 18) {                       // row update (J^T * (A J))
                int j = lane;
                for (int m2 = 0; m2 < 9; ++m2) {
                    int p = rp[m2], q = rq[m2];
                    float c = cb[m2], s = sb[m2];
                    float apj = A[p*19+j], aqj = A[q*19+j];
                    A[p*19+j] = c*apj - s*aqj;
                    A[q*19+j] = s*apj + c*aqj;
                }
            }
            __syncwarp();
        }
    }
}

// ---------------- K4: bn2 + covariance + Q/K/V projection + logm ----------------
__global__ __launch_bounds__(96) void k4(const float* __restrict__ g2,
                                         const float* __restrict__ be2,
                                         const float* __restrict__ Wq,
                                         const float* __restrict__ Wk,
                                         const float* __restrict__ Wv) {
    __shared__ float seg[C2*148];
    __shared__ float Cm[C2*C2];
    __shared__ float W3[3][C2*DOUT];
    __shared__ float A[3][18*19];
    __shared__ float V[3][18*19];
    __shared__ float mu[C2];
    __shared__ float sc2[C2], sh2[C2];
    __shared__ float cb[3][9], sb[3][9];
    __shared__ float invtr;
    __shared__ unsigned char pp[153], pq[153];

    int bx = blockIdx.x;
    int b = bx / 3, m = bx % 3;
    int off = (m == 0) ? 0 : (m == 1 ? 147 : 293);
    int L   = (m == 0) ? 147 : 146;
    int tid = threadIdx.x;

    if (tid < C2) {
        float mn = g_stats2[tid] / N2F;
        float v  = g_stats2[C2+tid] / N2F - mn*mn;
        float s  = rsqrtf(v + 1e-5f) * g2[tid];
        sc2[tid] = s; sh2[tid] = be2[tid] - mn*s;
    }
    for (int e = tid; e < C2*DOUT; e += 96) {
        W3[0][e] = Wq[e]; W3[1][e] = Wk[e]; W3[2][e] = Wv[e];
    }
    if (tid == 0) build_schedule(pp, pq);
    __syncthreads();

    for (int e = tid; e < C2*L; e += 96) {
        int r = e / L, t = e % L;
        seg[r*148 + t] = g_sig[(b*C2 + r)*T2 + off + t] * sc2[r] + sh2[r];
    }
    __syncthreads();
    if (tid < C2) {
        float s = 0.f;
        for (int t = 0; t < L; ++t) s += seg[tid*148 + t];
        mu[tid] = s / (float)L;
    }
    __syncthreads();

    float invLm1 = 1.f / (float)(L - 1);
    for (int pi = tid; pi < 210; pi += 96) {
        int i = 0, rem = pi;
        while (rem >= C2 - i) { rem -= C2 - i; ++i; }
        int j = i + rem;
        float d = 0.f;
        const float* ri = seg + i*148;
        const float* rj = seg + j*148;
        for (int t = 0; t < L; ++t) d += ri[t]*rj[t];
        float cv = (d - (float)L * mu[i]*mu[j]) * invLm1;
        Cm[i*C2 + j] = cv; Cm[j*C2 + i] = cv;
    }
    __syncthreads();
    if (tid == 0) {
        float tr = 0.f;
        for (int dd = 0; dd < C2; ++dd) tr += Cm[dd*C2 + dd];
        invtr = 1.f / tr;
    }
    __syncthreads();
    for (int e = tid; e < C2*C2; e += 96) {
        float v = Cm[e] * invtr;
        if (e / C2 == e % C2) v += 1e-5f;
        Cm[e] = v;
    }
    __syncthreads();

    // P = C @ W  (reuse seg as scratch: 3*20*18 = 1080 <= 2960)
    float* P = seg;
    for (int e = tid; e < 3*C2*DOUT; e += 96) {
        int xx = e / (C2*DOUT), rem = e % (C2*DOUT);
        int i = rem / DOUT, a = rem % DOUT;
        float s = 0.f;
        for (int j = 0; j < C2; ++j) s += Cm[i*C2 + j] * W3[xx][j*DOUT + a];
        P[e] = s;
    }
    __syncthreads();
    // A_x = W_x^T P_x  (18x18)
    for (int e = tid; e < 3*DOUT*DOUT; e += 96) {
        int xx = e / 324, rem = e % 324;
        int a = rem / DOUT, c = rem % DOUT;
        float s = 0.f;
        for (int i = 0; i < C2; ++i) s += W3[xx][i*DOUT + a] * P[xx*C2*DOUT + i*DOUT + c];
        A[xx][a*19 + c] = s;
    }
    __syncthreads();

    int w = tid >> 5, lane = tid & 31;
    jacobi18(A[w], V[w], cb[w], sb[w], pp, pq, lane);

    float* ev = Cm + w*20;     // C no longer needed; disjoint per warp
    if (lane < 18) ev[lane] = logf(fmaxf(A[w][lane*19 + lane], 1e-30f));
    __syncwarp();

    float* outp = (w == 0) ? g_logQ : (w == 1 ? g_logK : g_logV);
    outp += (size_t)bx * 324;
    const float* Vw = V[w];
    for (int e = lane; e < 324; e += 32) {
        int i = e / 18, j = e % 18;
        float s = 0.f;
        for (int k = 0; k < 18; ++k) s += Vw[i*19 + k] * ev[k] * Vw[j*19 + k];
        outp[e] = s;
    }
}

// ---------------- K5: log-distance attention + eigh(mean_log) + triu + linear ----------------
__global__ __launch_bounds__(96) void k5(const float* __restrict__ lw,
                                         const float* __restrict__ lb,
                                         float* __restrict__ out) {
    __shared__ float LQ[3][324], LK[3][324], LV[3][324];
    __shared__ float A[3][18*19], V[3][18*19];
    __shared__ float en[9], prob[9];
    __shared__ float feat[513];
    __shared__ float ev[3][18];
    __shared__ float cb[3][9], sb[3][9];
    __shared__ unsigned char pp[153], pq[153];

    int b = blockIdx.x, tid = threadIdx.x;
    if (tid == 0) build_schedule(pp, pq);
    for (int e = tid; e < 3*324; e += 96) {
        int m = e / 324, j = e % 324;
        LQ[m][j] = g_logQ[(b*3 + m)*324 + j];
        LK[m][j] = g_logK[(b*3 + m)*324 + j];
        LV[m][j] = g_logV[(b*3 + m)*324 + j];
    }
    __syncthreads();

    int w = tid >> 5, lane = tid & 31;
    for (int pe = w; pe < 9; pe += 3) {
        int i = pe / 3, j = pe % 3;
        float acc = 0.f;
        for (int e = lane; e < 324; e += 32) {
            float d = LK[i][e] - LQ[j][e];
            acc += d*d;
        }
#pragma unroll
        for (int off = 16; off; off >>= 1) acc += __shfl_xor_sync(0xffffffffu, acc, off);
        if (lane == 0) en[pe] = acc;
    }
    __syncthreads();
    if (tid == 0) {
        float f[9];
        for (int e = 0; e < 9; ++e) f[e] = 1.f / (1.f + log1pf(en[e]));
        for (int p = 0; p < 3; ++p) {      // softmax over K-index i, column p
            float f0 = f[0*3+p], f1 = f[1*3+p], f2 = f[2*3+p];
            float mx = fmaxf(f0, fmaxf(f1, f2));
            float e0 = expf(f0 - mx), e1 = expf(f1 - mx), e2 = expf(f2 - mx);
            float inv = 1.f / (e0 + e1 + e2);
            prob[p*3+0] = e0*inv; prob[p*3+1] = e1*inv; prob[p*3+2] = e2*inv;
        }
    }
    __syncthreads();

    {   // mean_log[p] for p = warp id
        float p0 = prob[w*3+0], p1 = prob[w*3+1], p2 = prob[w*3+2];
        for (int e = lane; e < 324; e += 32) {
            float ml = p0*LV[0][e] + p1*LV[1][e] + p2*LV[2][e];
            A[w][(e/18)*19 + (e%18)] = ml;
        }
    }
    __syncwarp();
    jacobi18(A[w], V[w], cb[w], sb[w], pp, pq, lane);
    if (lane < 18) ev[w][lane] = fmaxf(A[w][lane*19 + lane], LOG_RECT_EPS);
    __syncwarp();

    // upper-triangular features (np.triu_indices order), tang = V diag(ev) V^T
    for (int e = lane; e < 171; e += 32) {
        int i = 0, rem = e;
        while (rem >= 18 - i) { rem -= 18 - i; ++i; }
        int j = i + rem;
        float s = 0.f;
        for (int k = 0; k < 18; ++k) s += V[w][i*19 + k] * ev[w][k] * V[w][j*19 + k];
        feat[w*171 + e] = s;
    }
    __syncthreads();

    if (w == 0) {
        for (int c = 0; c < 4; ++c) {
            float acc = 0.f;
            for (int f = lane; f < 513; f += 32) acc += lw[c*513 + f] * feat[f];
#pragma unroll
            for (int off = 16; off; off >>= 1) acc += __shfl_xor_sync(0xffffffffu, acc, off);
            if (lane == 0) out[b*4 + c] = acc + lb[c];
        }
    }
}

// ---------------- launcher ----------------
extern "C" void kernel_launch(void* const* d_in, const int* in_sizes, int n_in,
                              void* d_out, int out_size) {
    const float* x   = (const float*)d_in[0];
    const float* w1  = (const float*)d_in[1];
    const float* b1  = (const float*)d_in[2];
    const float* g1  = (const float*)d_in[3];
    const float* be1 = (const float*)d_in[4];
    const float* w2  = (const float*)d_in[5];
    const float* b2  = (const float*)d_in[6];
    const float* g2  = (const float*)d_in[7];
    const float* be2 = (const float*)d_in[8];
    const float* Wq  = (const float*)d_in[9];
    const float* Wk  = (const float*)d_in[10];
    const float* Wv  = (const float*)d_in[11];
    const float* lw  = (const float*)d_in[12];
    const float* lb  = (const float*)d_in[13];

    size_t smem3 = (size_t)(C1*TPAD + C2*C1*12) * sizeof(float);
    cudaFuncSetAttribute(k3, cudaFuncAttributeMaxDynamicSharedMemorySize, (int)smem3);

    zero_stats<<<1, 64>>>();
    k1<<<B_, 256>>>(x, w1, b1);
    k3<<<B_, 256, smem3>>>(w2, b2, g1, be1);
    k3b<<<B_, 256>>>();
    k4<<<B_*3, 96>>>(g2, be2, Wq, Wk, Wv);
    k5<<<B_, 96>>>(lw, lb, (float*)d_out);
}

// round 2
// speedup vs baseline: 1.2293x; 1.2293x over previous
#include <cuda_runtime.h>
#include <math.h>

#define B_    1024
#define C1    22
#define T1    438
#define C2    20
#define T2    439
#define DOUT  18
#define TPAD  452
#define N1F   448512.0f
#define N2F   449536.0f
#define LOG_RECT_EPS (-9.210340371976184f)
#define NSWEEP 6

// ---------------- scratch (device globals: allocation-free) ----------------
__device__ float g_h1[B_*C1*T1];            // conv1 output (pre-bn1)
__device__ float g_sig[B_*C2*T2];           // conv2 output (pre-bn2)
__device__ float g_stats1[2*C1];            // sum / sumsq per channel
__device__ float g_stats2[2*C2];
__device__ float g_logQ[B_*3*DOUT*DOUT];
__device__ float g_logK[B_*3*DOUT*DOUT];
__device__ float g_logV[B_*3*DOUT*DOUT];

// ---------------- utility kernels ----------------
__global__ void zero_stats() {
    int t = threadIdx.x;
    if (t < 2*C1) g_stats1[t] = 0.f;
    if (t < 2*C2) g_stats2[t] = 0.f;
}

// ---------------- K1: conv1 (22x22 pointwise) + bn1 statistics ----------------
__global__ __launch_bounds__(256) void k1(const float* __restrict__ x,
                                          const float* __restrict__ w1,
                                          const float* __restrict__ b1) {
    int b = blockIdx.x, tid = threadIdx.x;
    __shared__ float sW[C1*C1];
    __shared__ float sb[C1];
    __shared__ float red[8][2*C1];
    for (int i = tid; i < C1*C1; i += 256) sW[i] = w1[i];
    if (tid < C1) sb[tid] = b1[tid];
    __syncthreads();

    float as[C1], aq[C1];
#pragma unroll
    for (int o = 0; o < C1; ++o) { as[o] = 0.f; aq[o] = 0.f; }

    for (int t = tid; t < T1; t += 256) {
        float xv[C1];
#pragma unroll
        for (int h = 0; h < C1; ++h) xv[h] = x[(b*C1 + h)*T1 + t];
#pragma unroll
        for (int o = 0; o < C1; ++o) {
            float v = sb[o];
#pragma unroll
            for (int h = 0; h < C1; ++h) v += sW[o*C1 + h] * xv[h];
            g_h1[(b*C1 + o)*T1 + t] = v;
            as[o] += v; aq[o] += v*v;
        }
    }
#pragma unroll
    for (int o = 0; o < C1; ++o) {
#pragma unroll
        for (int off = 16; off; off >>= 1) {
            as[o] += __shfl_xor_sync(0xffffffffu, as[o], off);
            aq[o] += __shfl_xor_sync(0xffffffffu, aq[o], off);
        }
    }
    int wid = tid >> 5, lane = tid & 31;
    if (lane == 0) {
#pragma unroll
        for (int o = 0; o < C1; ++o) { red[wid][o] = as[o]; red[wid][C1+o] = aq[o]; }
    }
    __syncthreads();
    if (tid < 2*C1) {
        float s = 0.f;
#pragma unroll
        for (int w = 0; w < 8; ++w) s += red[w][tid];
        atomicAdd(&g_stats1[tid], s);
    }
}

// ---------------- K3: bn1 + conv2 (12-tap, pad 6) -> g_sig + bn2 stats ----------------
__global__ __launch_bounds__(256) void k3(const float* __restrict__ w2,
                                          const float* __restrict__ b2,
                                          const float* __restrict__ g1,
                                          const float* __restrict__ be1) {
    extern __shared__ float sm[];
    float* sIn = sm;                 // C1*TPAD  (bn1'd, zero-padded by 6+pad)
    float* sw  = sm + C1*TPAD;       // 20*22*12 weights
    __shared__ float sc[C1], sh[C1], sb2[C2];
    __shared__ float s2[2*C2];
    int b = blockIdx.x, tid = threadIdx.x;

    if (tid < C1) {
        float m = g_stats1[tid] / N1F;
        float v = g_stats1[C1+tid] / N1F - m*m;
        float s = rsqrtf(v + 1e-5f) * g1[tid];
        sc[tid] = s; sh[tid] = be1[tid] - m*s;
    }
    if (tid < C2) sb2[tid] = b2[tid];
    if (tid < 2*C2) s2[tid] = 0.f;
    for (int i = tid; i < C2*C1*12; i += 256) sw[i] = w2[i];
    __syncthreads();

    for (int e = tid; e < C1*TPAD; e += 256) {
        int c = e / TPAD, tt = e % TPAD, t = tt - 6;
        float v = 0.f;
        if ((unsigned)t < (unsigned)T1) v = g_h1[(b*C1 + c)*T1 + t]*sc[c] + sh[c];
        sIn[e] = v;
    }
    __syncthreads();

    // units: (o, block of 8 output positions); 20 * 55 = 1100
    for (int u = tid; u < C2*55; u += 256) {
        int o = u / 55, tb = u % 55, tp0 = tb*8;
        float acc[8];
#pragma unroll
        for (int j = 0; j < 8; ++j) acc[j] = sb2[o];
        const float* wrow = sw + o*(C1*12);
#pragma unroll 1
        for (int i = 0; i < C1; ++i) {
            float win[19];
            const float* inr = sIn + i*TPAD + tp0;
#pragma unroll
            for (int j = 0; j < 19; ++j) win[j] = inr[j];
#pragma unroll
            for (int k = 0; k < 12; ++k) {
                float wv = wrow[i*12 + k];
#pragma unroll
                for (int j = 0; j < 8; ++j) acc[j] += wv * win[k+j];
            }
        }
        float ls = 0.f, lq = 0.f;
#pragma unroll
        for (int j = 0; j < 8; ++j) {
            int tp = tp0 + j;
            if (tp < T2) {
                g_sig[(b*C2 + o)*T2 + tp] = acc[j];
                ls += acc[j]; lq += acc[j]*acc[j];
            }
        }
        atomicAdd(&s2[o], ls);
        atomicAdd(&s2[C2+o], lq);
    }
    __syncthreads();
    if (tid < 2*C2) atomicAdd(&g_stats2[tid], s2[tid]);
}

// ---------------- parallel-order Jacobi eigensolver (18x18, one warp) ----------------
__device__ __forceinline__ void build_schedule(unsigned char* pp, unsigned char* pq) {
    int a[18];
    for (int i = 0; i < 18; ++i) a[i] = i;
    for (int r = 0; r < 17; ++r) {
        for (int k = 0; k < 9; ++k) {
            int x = a[k], y = a[17-k];
            pp[r*9 + k] = (unsigned char)(x < y ? x : y);
            pq[r*9 + k] = (unsigned char)(x < y ? y : x);
        }
        int last = a[17];
        for (int i = 17; i >= 2; --i) a[i] = a[i-1];
        a[1] = last;
    }
}

// A, V: 18x18 stored with row stride 19 in shared memory.
// All 9 rotations of a parallel round touch disjoint rows/cols ->
// the 162 A-col items, 162 V-col items, 162 A-row items are independent;
// distribute over all 32 lanes.
__device__ __forceinline__ void jacobi18(float* A, float* V, float* cb, float* sb,
                                         const unsigned char* pp, const unsigned char* pq,
                                         int lane) {
    for (int e = lane; e < 18*18; e += 32) {
        int i = e/18, j = e%18;
        V[i*19 + j] = (i == j) ? 1.f : 0.f;
    }
    __syncwarp();
    for (int sweep = 0; sweep < NSWEEP; ++sweep) {
        for (int r = 0; r < 17; ++r) {
            const unsigned char* rp = pp + r*9;
            const unsigned char* rq = pq + r*9;
            if (lane < 9) {
                int p = rp[lane], q = rq[lane];
                float apq = A[p*19 + q];
                float c = 1.f, s = 0.f;
                if (fabsf(apq) > 1e-35f) {
                    float theta = 0.5f*(A[q*19+q] - A[p*19+p]) / apq;
                    float t = 1.f/(fabsf(theta) + sqrtf(theta*theta + 1.f));
                    t = (theta < 0.f) ? -t : t;
                    c = rsqrtf(t*t + 1.f);
                    s = t*c;
                }
                cb[lane] = c; sb[lane] = s;
            }
            __syncwarp();
            // column update: 324 independent items (162 on A, 162 on V)
#pragma unroll
            for (int it = 0; it < 11; ++it) {
                int e = lane + it*32;
                if (e < 324) {
                    float* M = (e >= 162) ? V : A;
                    int idx = (e >= 162) ? e - 162 : e;
                    int m2 = idx / 18, k = idx % 18;
                    int p = rp[m2], q = rq[m2];
                    float c = cb[m2], s = sb[m2];
                    float mp = M[k*19+p], mq = M[k*19+q];
                    M[k*19+p] = c*mp - s*mq;
                    M[k*19+q] = s*mp + c*mq;
                }
            }
            __syncwarp();
            // row update: 162 independent items on A
#pragma unroll
            for (int it = 0; it < 6; ++it) {
                int e = lane + it*32;
                if (e < 162) {
                    int m2 = e / 18, j = e % 18;
                    int p = rp[m2], q = rq[m2];
                    float c = cb[m2], s = sb[m2];
                    float ap = A[p*19+j], aq2 = A[q*19+j];
                    A[p*19+j] = c*ap - s*aq2;
                    A[q*19+j] = s*ap + c*aq2;
                }
            }
            __syncwarp();
        }
    }
}

// ---------------- K4: bn2 + covariance + Q/K/V projection + logm ----------------
__global__ __launch_bounds__(96) void k4(const float* __restrict__ g2,
                                         const float* __restrict__ be2,
                                         const float* __restrict__ Wq,
                                         const float* __restrict__ Wk,
                                         const float* __restrict__ Wv) {
    __shared__ float seg[C2*148];
    __shared__ float Cm[C2*C2];
    __shared__ float W3[3][C2*DOUT];
    __shared__ float A[3][18*19];
    __shared__ float V[3][18*19];
    __shared__ float mu[C2];
    __shared__ float sc2[C2], sh2[C2];
    __shared__ float cb[3][9], sb[3][9];
    __shared__ float invtr;
    __shared__ unsigned char pp[153], pq[153];

    int bx = blockIdx.x;
    int b = bx / 3, m = bx % 3;
    int off = (m == 0) ? 0 : (m == 1 ? 147 : 293);
    int L   = (m == 0) ? 147 : 146;
    int tid = threadIdx.x;

    if (tid < C2) {
        float mn = g_stats2[tid] / N2F;
        float v  = g_stats2[C2+tid] / N2F - mn*mn;
        float s  = rsqrtf(v + 1e-5f) * g2[tid];
        sc2[tid] = s; sh2[tid] = be2[tid] - mn*s;
    }
    for (int e = tid; e < C2*DOUT; e += 96) {
        W3[0][e] = Wq[e]; W3[1][e] = Wk[e]; W3[2][e] = Wv[e];
    }
    if (tid == 0) build_schedule(pp, pq);
    __syncthreads();

    for (int e = tid; e < C2*L; e += 96) {
        int r = e / L, t = e % L;
        seg[r*148 + t] = g_sig[(b*C2 + r)*T2 + off + t] * sc2[r] + sh2[r];
    }
    __syncthreads();
    if (tid < C2) {
        float s = 0.f;
        for (int t = 0; t < L; ++t) s += seg[tid*148 + t];
        mu[tid] = s / (float)L;
    }
    __syncthreads();

    float invLm1 = 1.f / (float)(L - 1);
    for (int pi = tid; pi < 210; pi += 96) {
        int i = 0, rem = pi;
        while (rem >= C2 - i) { rem -= C2 - i; ++i; }
        int j = i + rem;
        float d = 0.f;
        const float* ri = seg + i*148;
        const float* rj = seg + j*148;
        for (int t = 0; t < L; ++t) d += ri[t]*rj[t];
        float cv = (d - (float)L * mu[i]*mu[j]) * invLm1;
        Cm[i*C2 + j] = cv; Cm[j*C2 + i] = cv;
    }
    __syncthreads();
    if (tid == 0) {
        float tr = 0.f;
        for (int dd = 0; dd < C2; ++dd) tr += Cm[dd*C2 + dd];
        invtr = 1.f / tr;
    }
    __syncthreads();
    for (int e = tid; e < C2*C2; e += 96) {
        float v = Cm[e] * invtr;
        if (e / C2 == e % C2) v += 1e-5f;
        Cm[e] = v;
    }
    __syncthreads();

    // P = C @ W  (reuse seg as scratch: 3*20*18 = 1080 <= 2960)
    float* P = seg;
    for (int e = tid; e < 3*C2*DOUT; e += 96) {
        int xx = e / (C2*DOUT), rem = e % (C2*DOUT);
        int i = rem / DOUT, a = rem % DOUT;
        float s = 0.f;
        for (int j = 0; j < C2; ++j) s += Cm[i*C2 + j] * W3[xx][j*DOUT + a];
        P[e] = s;
    }
    __syncthreads();
    // A_x = W_x^T P_x  (18x18)
    for (int e = tid; e < 3*DOUT*DOUT; e += 96) {
        int xx = e / 324, rem = e % 324;
        int a = rem / DOUT, c = rem % DOUT;
        float s = 0.f;
        for (int i = 0; i < C2; ++i) s += W3[xx][i*DOUT + a] * P[xx*C2*DOUT + i*DOUT + c];
        A[xx][a*19 + c] = s;
    }
    __syncthreads();

    int w = tid >> 5, lane = tid & 31;
    jacobi18(A[w], V[w], cb[w], sb[w], pp, pq, lane);

    float* ev = Cm + w*20;     // C no longer needed; disjoint per warp
    if (lane < 18) ev[lane] = logf(fmaxf(A[w][lane*19 + lane], 1e-30f));
    __syncwarp();

    float* outp = (w == 0) ? g_logQ : (w == 1 ? g_logK : g_logV);
    outp += (size_t)bx * 324;
    const float* Vw = V[w];
    for (int e = lane; e < 324; e += 32) {
        int i = e / 18, j = e % 18;
        float s = 0.f;
        for (int k = 0; k < 18; ++k) s += Vw[i*19 + k] * ev[k] * Vw[j*19 + k];
        outp[e] = s;
    }
}

// ---------------- K5: log-distance attention + eigh(mean_log) + triu + linear ----------------
__global__ __launch_bounds__(96) void k5(const float* __restrict__ lw,
                                         const float* __restrict__ lb,
                                         float* __restrict__ out) {
    __shared__ float LQ[3][324], LK[3][324], LV[3][324];
    __shared__ float A[3][18*19], V[3][18*19];
    __shared__ float en[9], prob[9];
    __shared__ float feat[513];
    __shared__ float ev[3][18];
    __shared__ float cb[3][9], sb[3][9];
    __shared__ unsigned char pp[153], pq[153];

    int b = blockIdx.x, tid = threadIdx.x;
    if (tid == 0) build_schedule(pp, pq);
    for (int e = tid; e < 3*324; e += 96) {
        int m = e / 324, j = e % 324;
        LQ[m][j] = g_logQ[(b*3 + m)*324 + j];
        LK[m][j] = g_logK[(b*3 + m)*324 + j];
        LV[m][j] = g_logV[(b*3 + m)*324 + j];
    }
    __syncthreads();

    int w = tid >> 5, lane = tid & 31;
    for (int pe = w; pe < 9; pe += 3) {
        int i = pe / 3, j = pe % 3;
        float acc = 0.f;
        for (int e = lane; e < 324; e += 32) {
            float d = LK[i][e] - LQ[j][e];
            acc += d*d;
        }
#pragma unroll
        for (int off = 16; off; off >>= 1) acc += __shfl_xor_sync(0xffffffffu, acc, off);
        if (lane == 0) en[pe] = acc;
    }
    __syncthreads();
    if (tid == 0) {
        float f[9];
        for (int e = 0; e < 9; ++e) f[e] = 1.f / (1.f + log1pf(en[e]));
        for (int p = 0; p < 3; ++p) {      // softmax over K-index i, column p
            float f0 = f[0*3+p], f1 = f[1*3+p], f2 = f[2*3+p];
            float mx = fmaxf(f0, fmaxf(f1, f2));
            float e0 = expf(f0 - mx), e1 = expf(f1 - mx), e2 = expf(f2 - mx);
            float inv = 1.f / (e0 + e1 + e2);
            prob[p*3+0] = e0*inv; prob[p*3+1] = e1*inv; prob[p*3+2] = e2*inv;
        }
    }
    __syncthreads();

    {   // mean_log[p] for p = warp id
        float p0 = prob[w*3+0], p1 = prob[w*3+1], p2 = prob[w*3+2];
        for (int e = lane; e < 324; e += 32) {
            float ml = p0*LV[0][e] + p1*LV[1][e] + p2*LV[2][e];
            A[w][(e/18)*19 + (e%18)] = ml;
        }
    }
    __syncwarp();
    jacobi18(A[w], V[w], cb[w], sb[w], pp, pq, lane);
    if (lane < 18) ev[w][lane] = fmaxf(A[w][lane*19 + lane], LOG_RECT_EPS);
    __syncwarp();

    // upper-triangular features (np.triu_indices order), tang = V diag(ev) V^T
    for (int e = lane; e < 171; e += 32) {
        int i = 0, rem = e;
        while (rem >= 18 - i) { rem -= 18 - i; ++i; }
        int j = i + rem;
        float s = 0.f;
        for (int k = 0; k < 18; ++k) s += V[w][i*19 + k] * ev[w][k] * V[w][j*19 + k];
        feat[w*171 + e] = s;
    }
    __syncthreads();

    if (w == 0) {
        for (int c = 0; c < 4; ++c) {
            float acc = 0.f;
            for (int f = lane; f < 513; f += 32) acc += lw[c*513 + f] * feat[f];
#pragma unroll
            for (int off = 16; off; off >>= 1) acc += __shfl_xor_sync(0xffffffffu, acc, off);
            if (lane == 0) out[b*4 + c] = acc + lb[c];
        }
    }
}

// ---------------- launcher ----------------
extern "C" void kernel_launch(void* const* d_in, const int* in_sizes, int n_in,
                              void* d_out, int out_size) {
    const float* x   = (const float*)d_in[0];
    const float* w1  = (const float*)d_in[1];
    const float* b1  = (const float*)d_in[2];
    const float* g1  = (const float*)d_in[3];
    const float* be1 = (const float*)d_in[4];
    const float* w2  = (const float*)d_in[5];
    const float* b2  = (const float*)d_in[6];
    const float* g2  = (const float*)d_in[7];
    const float* be2 = (const float*)d_in[8];
    const float* Wq  = (const float*)d_in[9];
    const float* Wk  = (const float*)d_in[10];
    const float* Wv  = (const float*)d_in[11];
    const float* lw  = (const float*)d_in[12];
    const float* lb  = (const float*)d_in[13];

    size_t smem3 = (size_t)(C1*TPAD + C2*C1*12) * sizeof(float);
    cudaFuncSetAttribute(k3, cudaFuncAttributeMaxDynamicSharedMemorySize, (int)smem3);

    zero_stats<<<1, 64>>>();
    k1<<<B_, 256>>>(x, w1, b1);
    k3<<<B_, 256, smem3>>>(w2, b2, g1, be1);
    k4<<<B_*3, 96>>>(g2, be2, Wq, Wk, Wv);
    k5<<<B_, 96>>>(lw, lb, (float*)d_out);
}

// round 3
// speedup vs baseline: 2.0230x; 1.6457x over previous
#include <cuda_runtime.h>
#include <math.h>

#define B_    1024
#define C1    22
#define T1    438
#define C2    20
#define T2    439
#define DOUT  18
#define TPAD  452
#define N1F   448512.0f
#define N2F   449536.0f
#define LOG_RECT_EPS (-9.210340371976184f)
#define NSWEEP1 7
#define NSWEEP2 7

// ---------------- scratch ----------------
__device__ float g_h1[B_*C1*T1];
__device__ float g_sig[B_*C2*T2];
__device__ float g_stats1[2*C1];
__device__ float g_stats2[2*C2];

__global__ void zero_stats() {
    int t = threadIdx.x;
    if (t < 2*C1) g_stats1[t] = 0.f;
    if (t < 2*C2) g_stats2[t] = 0.f;
}

// ---------------- K1: conv1 (22x22 pointwise) + bn1 stats ----------------
__global__ __launch_bounds__(256) void k1(const float* __restrict__ x,
                                          const float* __restrict__ w1,
                                          const float* __restrict__ b1) {
    int b = blockIdx.x, tid = threadIdx.x;
    __shared__ float sW[C1*C1];
    __shared__ float sb[C1];
    __shared__ float red[8][2*C1];
    for (int i = tid; i < C1*C1; i += 256) sW[i] = w1[i];
    if (tid < C1) sb[tid] = b1[tid];
    __syncthreads();

    float as[C1], aq[C1];
#pragma unroll
    for (int o = 0; o < C1; ++o) { as[o] = 0.f; aq[o] = 0.f; }

    for (int t = tid; t < T1; t += 256) {
        float xv[C1];
#pragma unroll
        for (int h = 0; h < C1; ++h) xv[h] = x[(b*C1 + h)*T1 + t];
#pragma unroll
        for (int o = 0; o < C1; ++o) {
            float v = sb[o];
#pragma unroll
            for (int h = 0; h < C1; ++h) v += sW[o*C1 + h] * xv[h];
            g_h1[(b*C1 + o)*T1 + t] = v;
            as[o] += v; aq[o] += v*v;
        }
    }
#pragma unroll
    for (int o = 0; o < C1; ++o) {
#pragma unroll
        for (int off = 16; off; off >>= 1) {
            as[o] += __shfl_xor_sync(0xffffffffu, as[o], off);
            aq[o] += __shfl_xor_sync(0xffffffffu, aq[o], off);
        }
    }
    int wid = tid >> 5, lane = tid & 31;
    if (lane == 0) {
#pragma unroll
        for (int o = 0; o < C1; ++o) { red[wid][o] = as[o]; red[wid][C1+o] = aq[o]; }
    }
    __syncthreads();
    if (tid < 2*C1) {
        float s = 0.f;
#pragma unroll
        for (int w = 0; w < 8; ++w) s += red[w][tid];
        atomicAdd(&g_stats1[tid], s);
    }
}

// ---------------- K3: bn1 + conv2 (12-tap, pad 6) + bn2 stats ----------------
__global__ __launch_bounds__(256) void k3(const float* __restrict__ w2,
                                          const float* __restrict__ b2,
                                          const float* __restrict__ g1,
                                          const float* __restrict__ be1) {
    extern __shared__ float sm[];
    float* sIn = sm;
    float* sw  = sm + C1*TPAD;
    __shared__ float sc[C1], sh[C1], sb2[C2];
    __shared__ float s2[2*C2];
    int b = blockIdx.x, tid = threadIdx.x;

    if (tid < C1) {
        float m = g_stats1[tid] / N1F;
        float v = g_stats1[C1+tid] / N1F - m*m;
        float s = rsqrtf(v + 1e-5f) * g1[tid];
        sc[tid] = s; sh[tid] = be1[tid] - m*s;
    }
    if (tid < C2) sb2[tid] = b2[tid];
    if (tid < 2*C2) s2[tid] = 0.f;
    for (int i = tid; i < C2*C1*12; i += 256) sw[i] = w2[i];
    __syncthreads();

    for (int e = tid; e < C1*TPAD; e += 256) {
        int c = e / TPAD, tt = e % TPAD, t = tt - 6;
        float v = 0.f;
        if ((unsigned)t < (unsigned)T1) v = g_h1[(b*C1 + c)*T1 + t]*sc[c] + sh[c];
        sIn[e] = v;
    }
    __syncthreads();

    for (int u = tid; u < C2*55; u += 256) {
        int o = u / 55, tb = u % 55, tp0 = tb*8;
        float acc[8];
#pragma unroll
        for (int j = 0; j < 8; ++j) acc[j] = sb2[o];
        const float* wrow = sw + o*(C1*12);
#pragma unroll 1
        for (int i = 0; i < C1; ++i) {
            float win[19];
            const float* inr = sIn + i*TPAD + tp0;
#pragma unroll
            for (int j = 0; j < 19; ++j) win[j] = inr[j];
#pragma unroll
            for (int k = 0; k < 12; ++k) {
                float wv = wrow[i*12 + k];
#pragma unroll
                for (int j = 0; j < 8; ++j) acc[j] += wv * win[k+j];
            }
        }
        float ls = 0.f, lq = 0.f;
#pragma unroll
        for (int j = 0; j < 8; ++j) {
            int tp = tp0 + j;
            if (tp < T2) {
                g_sig[(b*C2 + o)*T2 + tp] = acc[j];
                ls += acc[j]; lq += acc[j]*acc[j];
            }
        }
        atomicAdd(&s2[o], ls);
        atomicAdd(&s2[C2+o], lq);
    }
    __syncthreads();
    if (tid < 2*C2) atomicAdd(&g_stats2[tid], s2[tid]);
}

// ---------------- one-sided (Hestenes) Jacobi, columns in registers ----------------
// 18 lanes each own one column of the (PD) matrix. Converged column = lambda * q.
__device__ __forceinline__ void jacobi1s(float b[18], const unsigned char* sched, int lane, int nsweep) {
#pragma unroll 1
    for (int sweep = 0; sweep < nsweep; ++sweep) {
#pragma unroll 1
        for (int r = 0; r < 17; ++r) {
            int partner = sched[r*32 + lane];
            float pb[18];
#pragma unroll
            for (int i = 0; i < 18; ++i) pb[i] = __shfl_sync(0xffffffffu, b[i], partner);
            float app = 0.f, apq = 0.f;
#pragma unroll
            for (int i = 0; i < 18; ++i) {
                app = fmaf(b[i], b[i], app);
                apq = fmaf(b[i], pb[i], apq);
            }
            float aqq = __shfl_sync(0xffffffffu, app, partner);
            bool lower = lane < partner;
            float dpp = lower ? app : aqq;
            float dqq = lower ? aqq : app;
            float c = 1.f, s = 0.f;
            if (fabsf(apq) > 1e-34f) {
                float theta = 0.5f*(dqq - dpp)/apq;
                float t = 1.f/(fabsf(theta) + sqrtf(fmaf(theta, theta, 1.f)));
                t = (theta < 0.f) ? -t : t;
                c = rsqrtf(fmaf(t, t, 1.f));
                s = t*c;
            }
            float sp = lower ? -s : s;   // p: c*b - s*pb ; q: c*b + s*pb
#pragma unroll
            for (int i = 0; i < 18; ++i) b[i] = fmaf(sp, pb[i], c*b[i]);
        }
    }
}

// smem float offsets
#define OFF_SEG   0        // 60*152 = 9120  (overlaid: P at 0 [3240], logs at 4096 [2916])
#define OFF_ES    9120     // 9*648 = 5832
#define OFF_CM    14952    // 3*400
#define OFF_W3    16152    // 3*360
#define OFF_FEAT  17232    // 513
#define OFF_EN    17745    // 9
#define OFF_PROB  17754    // 9
#define OFF_S2    17763    // 20
#define OFF_MU    17783    // 60
#define OFF_MISC  17843    // 4 (invtr per patch)
#define SMEM_FLOATS 17848
#define SMEM_BYTES  (SMEM_FLOATS*4 + 17*32 + 32)

// ---------------- K45: cov + QKV + 9 logm + attention + 3 eigh + feat + linear ----------------
__global__ __launch_bounds__(288) void k45(const float* __restrict__ g2,
                                           const float* __restrict__ Wq,
                                           const float* __restrict__ Wk,
                                           const float* __restrict__ Wv,
                                           const float* __restrict__ lw,
                                           const float* __restrict__ lb,
                                           float* __restrict__ out) {
    extern __shared__ float sm[];
    float* sseg = sm + OFF_SEG;
    float* ES   = sm + OFF_ES;
    float* Cm   = sm + OFF_CM;
    float* W3   = sm + OFF_W3;
    float* feat = sm + OFF_FEAT;
    float* en   = sm + OFF_EN;
    float* prob = sm + OFF_PROB;
    float* s2s  = sm + OFF_S2;
    float* mu   = sm + OFF_MU;
    float* misc = sm + OFF_MISC;
    unsigned char* sched = (unsigned char*)(sm + SMEM_FLOATS);
    float* P    = sseg;            // overlay (after cov consumed)
    float* logs = sseg + 4096;     // overlay

    int b = blockIdx.x, tid = threadIdx.x;
    int w = tid >> 5, lane = tid & 31;

    if (tid == 0) {   // round-robin partner table
        int a[18];
        for (int i = 0; i < 18; ++i) a[i] = i;
        for (int r = 0; r < 17; ++r) {
            for (int k = 0; k < 9; ++k) {
                int xx = a[k], yy = a[17-k];
                sched[r*32 + xx] = (unsigned char)yy;
                sched[r*32 + yy] = (unsigned char)xx;
            }
            for (int g = 18; g < 32; ++g) sched[r*32 + g] = (unsigned char)g;
            int last = a[17];
            for (int i = 17; i >= 2; --i) a[i] = a[i-1];
            a[1] = last;
        }
    }
    if (tid < C2) {   // bn2 scale only (shift cancels under mean subtraction)
        float mn = g_stats2[tid] / N2F;
        float v  = g_stats2[C2+tid] / N2F - mn*mn;
        s2s[tid] = rsqrtf(v + 1e-5f) * g2[tid];
    }
    for (int e = tid; e < C2*DOUT; e += 288) {
        W3[0*360 + e] = Wq[e]; W3[1*360 + e] = Wk[e]; W3[2*360 + e] = Wv[e];
    }
    // load signal, patch-major layout [60][152], zero-padded
    for (int e = tid; e < 60*152; e += 288) {
        int row = e / 152, col = e % 152;
        int p = row / 20, c = row % 20;
        int L = (p == 0) ? 147 : 146;
        int off = (p == 0) ? 0 : (p == 1 ? 147 : 293);
        sseg[e] = (col < L) ? g_sig[(b*C2 + c)*T2 + off + col] : 0.f;
    }
    __syncthreads();
    if (tid < 60) {
        int p = tid / 20, L = (p == 0) ? 147 : 146;
        float s = 0.f;
        const float* r = sseg + tid*152;
        for (int t = 0; t < L; ++t) s += r[t];
        mu[tid] = s / (float)L;
    }
    __syncthreads();
    for (int e = tid; e < 60*152; e += 288) {
        int row = e / 152, col = e % 152;
        int p = row / 20, L = (p == 0) ? 147 : 146;
        if (col < L) sseg[e] -= mu[row];
    }
    __syncthreads();

    // covariance: 3 patches x 210 pairs, float4 dot (padding is exactly zero)
    for (int u = tid; u < 630; u += 288) {
        int p = u / 210, pi = u % 210;
        int i = 0, rem = pi;
        while (rem >= C2 - i) { rem -= C2 - i; ++i; }
        int j = i + rem;
        const float4* ri = (const float4*)(sseg + (p*20 + i)*152);
        const float4* rj = (const float4*)(sseg + (p*20 + j)*152);
        float acc = 0.f;
#pragma unroll
        for (int t = 0; t < 38; ++t) {
            float4 a4 = ri[t], c4 = rj[t];
            acc += a4.x*c4.x + a4.y*c4.y + a4.z*c4.z + a4.w*c4.w;
        }
        float cv = acc * s2s[i] * s2s[j];
        Cm[p*400 + i*20 + j] = cv;
        Cm[p*400 + j*20 + i] = cv;
    }
    __syncthreads();
    if (tid < 3) {
        float tr = 0.f;
        for (int d = 0; d < C2; ++d) tr += Cm[tid*400 + d*21];
        misc[tid] = 1.f / tr;
    }
    __syncthreads();
    for (int e = tid; e < 3*400; e += 288) {
        int p = e / 400, r = e % 400;
        float v = Cm[e] * misc[p];
        if (r / 20 == r % 20) v += 1e-5f;
        Cm[e] = v;
    }
    __syncthreads();

    // warp w (0..8): patch p = w/3, proj x = w%3 ; P = C*W (20x18)
    int pp_ = w / 3, xx_ = w % 3;
    for (int e = lane; e < 360; e += 32) {
        int a = e / 18, j = e % 18;
        float s = 0.f;
        const float* crow = Cm + pp_*400 + a*20;
        const float* wcol = W3 + xx_*360;
        for (int c = 0; c < C2; ++c) s = fmaf(crow[c], wcol[c*18 + j], s);
        P[w*360 + e] = s;
    }
    __syncwarp();
    // A column j into registers: b[i] = sum_a W[a][i] * P[a][j]
    float bcol[18];
#pragma unroll
    for (int i = 0; i < 18; ++i) bcol[i] = 0.f;
    if (lane < 18) {
        const float* Pw = P + w*360;
        const float* Wx = W3 + xx_*360;
#pragma unroll 1
        for (int i = 0; i < 18; ++i) {
            float s = 0.f;
            for (int a = 0; a < C2; ++a) s = fmaf(Wx[a*18 + i], Pw[a*18 + lane], s);
            bcol[i] = s;
        }
    }
    __syncthreads();   // all P reads done before logs overlay is written

    jacobi1s(bcol, sched, lane, NSWEEP1);

    {   // logm: log(M) = sum_k (log(lam_k)/lam_k^2) b_k b_k^T,  lam^2 = ||b||^2
        float app = 0.f;
#pragma unroll
        for (int i = 0; i < 18; ++i) app = fmaf(bcol[i], bcol[i], app);
        if (lane < 18) {
            float lg = 0.5f * logf(fmaxf(app, 1e-38f));
            float coef = lg / app;
            float* Sk = ES + w*648 + lane*18;
            float* Bk = ES + w*648 + 324 + lane*18;
#pragma unroll
            for (int i = 0; i < 18; ++i) { Sk[i] = coef*bcol[i]; Bk[i] = bcol[i]; }
        }
        __syncwarp();
        const float* Sw = ES + w*648;
        const float* Bw = ES + w*648 + 324;
        for (int e = lane; e < 324; e += 32) {
            int i = e / 18, j = e % 18;
            float s = 0.f;
            for (int k = 0; k < 18; ++k) s = fmaf(Sw[k*18 + i], Bw[k*18 + j], s);
            logs[w*324 + e] = s;
        }
    }
    __syncthreads();

    // energies: pair (iK, jQ) per warp; logK = patch iK proj 1, logQ = patch jQ proj 0
    {
        int iK = w / 3, jQ = w % 3;
        const float* LK = logs + (iK*3 + 1)*324;
        const float* LQ = logs + (jQ*3 + 0)*324;
        float acc = 0.f;
        for (int e = lane; e < 324; e += 32) {
            float d = LK[e] - LQ[e];
            acc = fmaf(d, d, acc);
        }
#pragma unroll
        for (int off = 16; off; off >>= 1) acc += __shfl_xor_sync(0xffffffffu, acc, off);
        if (lane == 0) en[iK*3 + jQ] = acc;
    }
    __syncthreads();
    if (tid == 0) {
        float f[9];
        for (int e = 0; e < 9; ++e) f[e] = 1.f / (1.f + log1pf(en[e]));
        for (int p = 0; p < 3; ++p) {
            float f0 = f[0*3+p], f1 = f[1*3+p], f2 = f[2*3+p];
            float mx = fmaxf(f0, fmaxf(f1, f2));
            float e0 = expf(f0-mx), e1 = expf(f1-mx), e2 = expf(f2-mx);
            float inv = 1.f / (e0 + e1 + e2);
            prob[p*3+0] = e0*inv; prob[p*3+1] = e1*inv; prob[p*3+2] = e2*inv;
        }
    }
    __syncthreads();

    // wave2: warps 0..2 -> mean_log eigh (Gershgorin shift -> PD), feat
    if (w < 3) {
        float p0 = prob[w*3+0], p1 = prob[w*3+1], p2 = prob[w*3+2];
#pragma unroll
        for (int i = 0; i < 18; ++i) bcol[i] = 0.f;
        if (lane < 18) {
            const float* V0 = logs + 2*324;
            const float* V1 = logs + 5*324;
            const float* V2 = logs + 8*324;
#pragma unroll
            for (int i = 0; i < 18; ++i) {
                int e = i*18 + lane;
                bcol[i] = p0*V0[e] + p1*V1[e] + p2*V2[e];
            }
        }
        float bound = 1e30f;
        if (lane < 18) {
            float rs = 0.f;
#pragma unroll
            for (int i = 0; i < 18; ++i) rs += fabsf(bcol[i]);
            float dg = bcol[lane];
            bound = dg - (rs - fabsf(dg));
        }
#pragma unroll
        for (int off = 16; off; off >>= 1) bound = fminf(bound, __shfl_xor_sync(0xffffffffu, bound, off));
        float alpha = fmaxf(0.f, -bound) + 1.0f;
        if (lane < 18) bcol[lane] += alpha;

        jacobi1s(bcol, sched, lane, NSWEEP2);

        float app = 0.f;
#pragma unroll
        for (int i = 0; i < 18; ++i) app = fmaf(bcol[i], bcol[i], app);
        if (lane < 18) {
            float lamS = sqrtf(app);
            float ev = fmaxf(lamS - alpha, LOG_RECT_EPS);
            float coef = ev / fmaxf(app, 1e-38f);
            float* Sk = ES + w*648 + lane*18;
            float* Bk = ES + w*648 + 324 + lane*18;
#pragma unroll
            for (int i = 0; i < 18; ++i) { Sk[i] = coef*bcol[i]; Bk[i] = bcol[i]; }
        }
        __syncwarp();
        const float* Sw = ES + w*648;
        const float* Bw = ES + w*648 + 324;
        for (int e = lane; e < 171; e += 32) {
            int i = 0, rem = e;
            while (rem >= 18 - i) { rem -= 18 - i; ++i; }
            int j = i + rem;
            float s = 0.f;
            for (int k = 0; k < 18; ++k) s = fmaf(Sw[k*18 + i], Bw[k*18 + j], s);
            feat[w*171 + e] = s;
        }
    }
    __syncthreads();

    if (w < 4) {
        float acc = 0.f;
        for (int f = lane; f < 513; f += 32) acc = fmaf(lw[w*513 + f], feat[f], acc);
#pragma unroll
        for (int off = 16; off; off >>= 1) acc += __shfl_xor_sync(0xffffffffu, acc, off);
        if (lane == 0) out[b*4 + w] = acc + lb[w];
    }
}

// ---------------- launcher ----------------
extern "C" void kernel_launch(void* const* d_in, const int* in_sizes, int n_in,
                              void* d_out, int out_size) {
    const float* x   = (const float*)d_in[0];
    const float* w1  = (const float*)d_in[1];
    const float* b1  = (const float*)d_in[2];
    const float* g1  = (const float*)d_in[3];
    const float* be1 = (const float*)d_in[4];
    const float* w2  = (const float*)d_in[5];
    const float* b2  = (const float*)d_in[6];
    const float* g2  = (const float*)d_in[7];
    const float* lw  = (const float*)d_in[12];
    const float* lb  = (const float*)d_in[13];
    const float* Wq  = (const float*)d_in[9];
    const float* Wk  = (const float*)d_in[10];
    const float* Wv  = (const float*)d_in[11];

    size_t smem3 = (size_t)(C1*TPAD + C2*C1*12) * sizeof(float);
    cudaFuncSetAttribute(k3, cudaFuncAttributeMaxDynamicSharedMemorySize, (int)smem3);
    cudaFuncSetAttribute(k45, cudaFuncAttributeMaxDynamicSharedMemorySize, SMEM_BYTES);

    zero_stats<<<1, 64>>>();
    k1<<<B_, 256>>>(x, w1, b1);
    k3<<<B_, 256, smem3>>>(w2, b2, g1, be1);
    k45<<<B_, 288, SMEM_BYTES>>>(g2, Wq, Wk, Wv, lw, lb, (float*)d_out);
}

// round 4
// speedup vs baseline: 2.8087x; 1.3884x over previous
#include <cuda_runtime.h>
#include <math.h>

#define B_    1024
#define C1    22
#define T1    438
#define C2    20
#define T2    439
#define TPAD  452
#define DOUT  18
#define N1F   448512.0
#define N2F   449536.0f
#define LOG_RECT_EPS (-9.210340371976184f)
#define NSWEEP1 6
#define NSWEEP2 6

// ---------------- scratch ----------------
__device__ float  g_sig[B_*C2*T2];
__device__ double g_mx[C1];          // sum of x per channel
__device__ double g_mom[253];        // packed upper-tri sum x_h x_h'
__device__ float  g_stats2[2*C2];
__device__ float  g_weff[C2*C1*12];  // folded conv weights
__device__ float  g_csum[C2*13];     // tap-bias prefix sums
__device__ float  g_b2f[C2];

__global__ void zero_stats() {
    int t = threadIdx.x;
    if (t < C1) g_mx[t] = 0.0;
    if (t < 2*C2) g_stats2[t] = 0.f;
    for (int e = t; e < 253; e += 320) g_mom[e] = 0.0;
}

// ---------------- K0: x channel moments (for analytic bn1 stats) ----------------
__global__ __launch_bounds__(256) void k0(const float* __restrict__ x) {
    __shared__ float xp[C1*440];
    int b = blockIdx.x, tid = threadIdx.x;
    for (int e = tid; e < C1*440; e += 256) {
        int c = e / 440, tt = e % 440;
        xp[e] = (tt < T1) ? x[(b*C1 + c)*T1 + tt] : 0.f;
    }
    __syncthreads();
    for (int u = tid; u < 275; u += 256) {
        if (u < 253) {
            int i = 0, rem = u;
            while (rem >= C1 - i) { rem -= C1 - i; ++i; }
            int j = i + rem;
            const float4* ri = (const float4*)(xp + i*440);
            const float4* rj = (const float4*)(xp + j*440);
            float acc = 0.f;
#pragma unroll
            for (int t = 0; t < 110; ++t) {
                float4 a4 = ri[t], c4 = rj[t];
                acc += a4.x*c4.x + a4.y*c4.y + a4.z*c4.z + a4.w*c4.w;
            }
            atomicAdd(&g_mom[u], (double)acc);
        } else {
            int c = u - 253;
            float s = 0.f;
            const float* r = xp + c*440;
            for (int t = 0; t < T1; ++t) s += r[t];
            atomicAdd(&g_mx[c], (double)s);
        }
    }
}

// ---------------- KW: fold bn1 into conv weights (1 block) ----------------
__global__ __launch_bounds__(256) void kw(const float* __restrict__ w1,
                                          const float* __restrict__ b1,
                                          const float* __restrict__ g1,
                                          const float* __restrict__ be1,
                                          const float* __restrict__ w2,
                                          const float* __restrict__ b2) {
    __shared__ float s1[C1], t1[C1];
    __shared__ double mxs[C1];
    int tid = threadIdx.x;
    if (tid < C1) mxs[tid] = g_mx[tid] / N1F;
    __syncthreads();
    if (tid < C1) {
        int c = tid;
        double d = 0.0;
        for (int h = 0; h < C1; ++h) d += (double)w1[c*C1 + h] * mxs[h];
        double q = 0.0;
        for (int h = 0; h < C1; ++h) {
            double wh = (double)w1[c*C1 + h];
            for (int hp = 0; hp < C1; ++hp) {
                int a = h < hp ? h : hp, bb = h < hp ? hp : h;
                int idx = a*C1 - a*(a-1)/2 + (bb - a);
                double G = g_mom[idx] / N1F - mxs[h]*mxs[hp];
                q += wh * (double)w1[c*C1 + hp] * G;
            }
        }
        double var = q;
        float s = (float)(rsqrt(var + 1e-5) ) * g1[c];
        float mean1 = (float)d + b1[c];
        s1[c] = s;
        t1[c] = be1[c] - mean1 * s;
    }
    __syncthreads();
    for (int e = tid; e < C2*C1*12; e += 256) {
        int o = e / (C1*12), r = e % (C1*12);
        int h = r / 12, k = r % 12;
        float s = 0.f;
        for (int i = 0; i < C1; ++i)
            s = fmaf(w2[(o*C1 + i)*12 + k] * s1[i], w1[i*C1 + h], s);
        g_weff[(o*C1 + h)*12 + k] = s;
    }
    if (tid < C2) {
        int o = tid;
        float cs = 0.f;
        g_csum[o*13 + 0] = 0.f;
        for (int k = 0; k < 12; ++k) {
            float tb = 0.f;
            for (int i = 0; i < C1; ++i) tb = fmaf(w2[(o*C1 + i)*12 + k], t1[i], tb);
            cs += tb;
            g_csum[o*13 + k + 1] = cs;
        }
        g_b2f[o] = b2[o];
    }
}

// ---------------- K13: fused conv (22->20ch, 12 taps) on x + bn2 stats ----------------
__global__ __launch_bounds__(256) void k13(const float* __restrict__ x) {
    extern __shared__ float sm[];
    float* xp = sm;                  // C1*TPAD, zero-padded by 6 both sides
    float* sw = sm + C1*TPAD;        // 5280 folded weights
    __shared__ float csumS[C2*13], sb2[C2], s2[2*C2];
    int b = blockIdx.x, tid = threadIdx.x;

    for (int e = tid; e < C2*13; e += 256) csumS[e] = g_csum[e];
    if (tid < C2) sb2[tid] = g_b2f[tid];
    if (tid < 2*C2) s2[tid] = 0.f;
    for (int e = tid; e < C2*C1*12; e += 256) sw[e] = g_weff[e];
    for (int e = tid; e < C1*TPAD; e += 256) {
        int c = e / TPAD, tt = e % TPAD, t = tt - 6;
        xp[e] = ((unsigned)t < (unsigned)T1) ? x[(b*C1 + c)*T1 + t] : 0.f;
    }
    __syncthreads();

    for (int u = tid; u < C2*55; u += 256) {
        int o = u / 55, tb = u % 55, tp0 = tb*8;
        float acc[8];
#pragma unroll
        for (int j = 0; j < 8; ++j) acc[j] = 0.f;
#pragma unroll 1
        for (int i = 0; i < C1; ++i) {
            float win[20];
            const float4* inr4 = (const float4*)(xp + i*TPAD + tp0);
#pragma unroll
            for (int m = 0; m < 5; ++m) {
                float4 v = inr4[m];
                win[4*m+0] = v.x; win[4*m+1] = v.y; win[4*m+2] = v.z; win[4*m+3] = v.w;
            }
            float wf[12];
            const float4* w4 = (const float4*)(sw + (o*C1 + i)*12);
#pragma unroll
            for (int m = 0; m < 3; ++m) {
                float4 v = w4[m];
                wf[4*m+0] = v.x; wf[4*m+1] = v.y; wf[4*m+2] = v.z; wf[4*m+3] = v.w;
            }
#pragma unroll
            for (int k = 0; k < 12; ++k) {
#pragma unroll
                for (int j = 0; j < 8; ++j) acc[j] = fmaf(wf[k], win[k+j], acc[j]);
            }
        }
        float ls = 0.f, lq = 0.f;
#pragma unroll
        for (int j = 0; j < 8; ++j) {
            int tp = tp0 + j;
            if (tp < T2) {
                int kmin = 6 - tp; kmin = kmin < 0 ? 0 : kmin;
                int kmax = 443 - tp; kmax = kmax > 11 ? 11 : kmax;
                float v = acc[j] + sb2[o] + csumS[o*13 + kmax + 1] - csumS[o*13 + kmin];
                g_sig[(b*C2 + o)*T2 + tp] = v;
                ls += v; lq += v*v;
            }
        }
        atomicAdd(&s2[o], ls);
        atomicAdd(&s2[C2+o], lq);
    }
    __syncthreads();
    if (tid < 2*C2) atomicAdd(&g_stats2[tid], s2[tid]);
}

// ---------------- one-sided (Hestenes) Jacobi, columns in registers ----------------
__device__ __forceinline__ void jacobi1s(float b[18], const unsigned char* sched, int lane, int nsweep) {
#pragma unroll 1
    for (int sweep = 0; sweep < nsweep; ++sweep) {
#pragma unroll 1
        for (int r = 0; r < 17; ++r) {
            int partner = sched[r*32 + lane];
            float pb[18];
#pragma unroll
            for (int i = 0; i < 18; ++i) pb[i] = __shfl_sync(0xffffffffu, b[i], partner);
            float app = 0.f, apq = 0.f;
#pragma unroll
            for (int i = 0; i < 18; ++i) {
                app = fmaf(b[i], b[i], app);
                apq = fmaf(b[i], pb[i], apq);
            }
            float aqq = __shfl_sync(0xffffffffu, app, partner);
            bool lower = lane < partner;
            float dpp = lower ? app : aqq;
            float dqq = lower ? aqq : app;
            float c = 1.f, s = 0.f;
            if (fabsf(apq) > 1e-34f) {
                float theta = 0.5f*(dqq - dpp)/apq;
                float t = 1.f/(fabsf(theta) + sqrtf(fmaf(theta, theta, 1.f)));
                t = (theta < 0.f) ? -t : t;
                c = rsqrtf(fmaf(t, t, 1.f));
                s = t*c;
            }
            float sp = lower ? -s : s;
#pragma unroll
            for (int i = 0; i < 18; ++i) b[i] = fmaf(sp, pb[i], c*b[i]);
        }
    }
}

// smem float offsets (k45)
#define OFF_SEG   0
#define OFF_ES    9120
#define OFF_CM    14952
#define OFF_W3    16152
#define OFF_FEAT  17232
#define OFF_EN    17745
#define OFF_PROB  17754
#define OFF_S2    17763
#define OFF_MU    17783
#define OFF_MISC  17843
#define SMEM_FLOATS 17848
#define SMEM_BYTES  (SMEM_FLOATS*4 + 17*32 + 32)

// ---------------- K45: cov + QKV + 9 logm + attention + 3 eigh + feat + linear ----------------
__global__ __launch_bounds__(288) void k45(const float* __restrict__ g2,
                                           const float* __restrict__ Wq,
                                           const float* __restrict__ Wk,
                                           const float* __restrict__ Wv,
                                           const float* __restrict__ lw,
                                           const float* __restrict__ lb,
                                           float* __restrict__ out) {
    extern __shared__ float sm[];
    float* sseg = sm + OFF_SEG;
    float* ES   = sm + OFF_ES;
    float* Cm   = sm + OFF_CM;
    float* W3   = sm + OFF_W3;
    float* feat = sm + OFF_FEAT;
    float* en   = sm + OFF_EN;
    float* prob = sm + OFF_PROB;
    float* s2s  = sm + OFF_S2;
    float* mu   = sm + OFF_MU;
    float* misc = sm + OFF_MISC;
    unsigned char* sched = (unsigned char*)(sm + SMEM_FLOATS);
    float* P    = sseg;
    float* logs = sseg + 4096;

    int b = blockIdx.x, tid = threadIdx.x;
    int w = tid >> 5, lane = tid & 31;

    if (tid == 0) {
        int a[18];
        for (int i = 0; i < 18; ++i) a[i] = i;
        for (int r = 0; r < 17; ++r) {
            for (int k = 0; k < 9; ++k) {
                int xx = a[k], yy = a[17-k];
                sched[r*32 + xx] = (unsigned char)yy;
                sched[r*32 + yy] = (unsigned char)xx;
            }
            for (int g = 18; g < 32; ++g) sched[r*32 + g] = (unsigned char)g;
            int last = a[17];
            for (int i = 17; i >= 2; --i) a[i] = a[i-1];
            a[1] = last;
        }
    }
    if (tid < C2) {
        float mn = g_stats2[tid] / N2F;
        float v  = g_stats2[C2+tid] / N2F - mn*mn;
        s2s[tid] = rsqrtf(v + 1e-5f) * g2[tid];
    }
    for (int e = tid; e < C2*DOUT; e += 288) {
        W3[0*360 + e] = Wq[e]; W3[1*360 + e] = Wk[e]; W3[2*360 + e] = Wv[e];
    }
    for (int e = tid; e < 60*152; e += 288) {
        int row = e / 152, col = e % 152;
        int p = row / 20, c = row % 20;
        int L = (p == 0) ? 147 : 146;
        int off = (p == 0) ? 0 : (p == 1 ? 147 : 293);
        sseg[e] = (col < L) ? g_sig[(b*C2 + c)*T2 + off + col] : 0.f;
    }
    __syncthreads();
    if (tid < 60) {
        int p = tid / 20, L = (p == 0) ? 147 : 146;
        float s = 0.f;
        const float* r = sseg + tid*152;
        for (int t = 0; t < L; ++t) s += r[t];
        mu[tid] = s / (float)L;
    }
    __syncthreads();
    for (int e = tid; e < 60*152; e += 288) {
        int row = e / 152, col = e % 152;
        int p = row / 20, L = (p == 0) ? 147 : 146;
        if (col < L) sseg[e] -= mu[row];
    }
    __syncthreads();

    for (int u = tid; u < 630; u += 288) {
        int p = u / 210, pi = u % 210;
        int i = 0, rem = pi;
        while (rem >= C2 - i) { rem -= C2 - i; ++i; }
        int j = i + rem;
        const float4* ri = (const float4*)(sseg + (p*20 + i)*152);
        const float4* rj = (const float4*)(sseg + (p*20 + j)*152);
        float acc = 0.f;
#pragma unroll
        for (int t = 0; t < 38; ++t) {
            float4 a4 = ri[t], c4 = rj[t];
            acc += a4.x*c4.x + a4.y*c4.y + a4.z*c4.z + a4.w*c4.w;
        }
        float cv = acc * s2s[i] * s2s[j];
        Cm[p*400 + i*20 + j] = cv;
        Cm[p*400 + j*20 + i] = cv;
    }
    __syncthreads();
    if (tid < 3) {
        float tr = 0.f;
        for (int d = 0; d < C2; ++d) tr += Cm[tid*400 + d*21];
        misc[tid] = 1.f / tr;
    }
    __syncthreads();
    for (int e = tid; e < 3*400; e += 288) {
        int p = e / 400, r = e % 400;
        float v = Cm[e] * misc[p];
        if (r / 20 == r % 20) v += 1e-5f;
        Cm[e] = v;
    }
    __syncthreads();

    int pp_ = w / 3, xx_ = w % 3;
    for (int e = lane; e < 360; e += 32) {
        int a = e / 18, j = e % 18;
        float s = 0.f;
        const float* crow = Cm + pp_*400 + a*20;
        const float* wcol = W3 + xx_*360;
        for (int c = 0; c < C2; ++c) s = fmaf(crow[c], wcol[c*18 + j], s);
        P[w*360 + e] = s;
    }
    __syncwarp();
    float bcol[18];
#pragma unroll
    for (int i = 0; i < 18; ++i) bcol[i] = 0.f;
    if (lane < 18) {
        const float* Pw = P + w*360;
        const float* Wx = W3 + xx_*360;
#pragma unroll 1
        for (int i = 0; i < 18; ++i) {
            float s = 0.f;
            for (int a = 0; a < C2; ++a) s = fmaf(Wx[a*18 + i], Pw[a*18 + lane], s);
            bcol[i] = s;
        }
    }
    __syncthreads();

    jacobi1s(bcol, sched, lane, NSWEEP1);

    {
        float app = 0.f;
#pragma unroll
        for (int i = 0; i < 18; ++i) app = fmaf(bcol[i], bcol[i], app);
        if (lane < 18) {
            float lg = 0.5f * logf(fmaxf(app, 1e-38f));
            float coef = lg / app;
            float* Sk = ES + w*648 + lane*18;
            float* Bk = ES + w*648 + 324 + lane*18;
#pragma unroll
            for (int i = 0; i < 18; ++i) { Sk[i] = coef*bcol[i]; Bk[i] = bcol[i]; }
        }
        __syncwarp();
        const float* Sw = ES + w*648;
        const float* Bw = ES + w*648 + 324;
        for (int e = lane; e < 324; e += 32) {
            int i = e / 18, j = e % 18;
            float s = 0.f;
            for (int k = 0; k < 18; ++k) s = fmaf(Sw[k*18 + i], Bw[k*18 + j], s);
            logs[w*324 + e] = s;
        }
    }
    __syncthreads();

    {
        int iK = w / 3, jQ = w % 3;
        const float* LK = logs + (iK*3 + 1)*324;
        const float* LQ = logs + (jQ*3 + 0)*324;
        float acc = 0.f;
        for (int e = lane; e < 324; e += 32) {
            float d = LK[e] - LQ[e];
            acc = fmaf(d, d, acc);
        }
#pragma unroll
        for (int off = 16; off; off >>= 1) acc += __shfl_xor_sync(0xffffffffu, acc, off);
        if (lane == 0) en[iK*3 + jQ] = acc;
    }
    __syncthreads();
    if (tid == 0) {
        float f[9];
        for (int e = 0; e < 9; ++e) f[e] = 1.f / (1.f + log1pf(en[e]));
        for (int p = 0; p < 3; ++p) {
            float f0 = f[0*3+p], f1 = f[1*3+p], f2 = f[2*3+p];
            float mx = fmaxf(f0, fmaxf(f1, f2));
            float e0 = expf(f0-mx), e1 = expf(f1-mx), e2 = expf(f2-mx);
            float inv = 1.f / (e0 + e1 + e2);
            prob[p*3+0] = e0*inv; prob[p*3+1] = e1*inv; prob[p*3+2] = e2*inv;
        }
    }
    __syncthreads();

    if (w < 3) {
        float p0 = prob[w*3+0], p1 = prob[w*3+1], p2 = prob[w*3+2];
#pragma unroll
        for (int i = 0; i < 18; ++i) bcol[i] = 0.f;
        if (lane < 18) {
            const float* V0 = logs + 2*324;
            const float* V1 = logs + 5*324;
            const float* V2 = logs + 8*324;
#pragma unroll
            for (int i = 0; i < 18; ++i) {
                int e = i*18 + lane;
                bcol[i] = p0*V0[e] + p1*V1[e] + p2*V2[e];
            }
        }
        float bound = 1e30f;
        if (lane < 18) {
            float rs = 0.f;
#pragma unroll
            for (int i = 0; i < 18; ++i) rs += fabsf(bcol[i]);
            float dg = bcol[lane];
            bound = dg - (rs - fabsf(dg));
        }
#pragma unroll
        for (int off = 16; off; off >>= 1) bound = fminf(bound, __shfl_xor_sync(0xffffffffu, bound, off));
        float alpha = fmaxf(0.f, -bound) + 1.0f;
        if (lane < 18) bcol[lane] += alpha;

        jacobi1s(bcol, sched, lane, NSWEEP2);

        float app = 0.f;
#pragma unroll
        for (int i = 0; i < 18; ++i) app = fmaf(bcol[i], bcol[i], app);
        if (lane < 18) {
            float lamS = sqrtf(app);
            float ev = fmaxf(lamS - alpha, LOG_RECT_EPS);
            float coef = ev / fmaxf(app, 1e-38f);
            float* Sk = ES + w*648 + lane*18;
            float* Bk = ES + w*648 + 324 + lane*18;
#pragma unroll
            for (int i = 0; i < 18; ++i) { Sk[i] = coef*bcol[i]; Bk[i] = bcol[i]; }
        }
        __syncwarp();
        const float* Sw = ES + w*648;
        const float* Bw = ES + w*648 + 324;
        for (int e = lane; e < 171; e += 32) {
            int i = 0, rem = e;
            while (rem >= 18 - i) { rem -= 18 - i; ++i; }
            int j = i + rem;
            float s = 0.f;
            for (int k = 0; k < 18; ++k) s = fmaf(Sw[k*18 + i], Bw[k*18 + j], s);
            feat[w*171 + e] = s;
        }
    }
    __syncthreads();

    if (w < 4) {
        float acc = 0.f;
        for (int f = lane; f < 513; f += 32) acc = fmaf(lw[w*513 + f], feat[f], acc);
#pragma unroll
        for (int off = 16; off; off >>= 1) acc += __shfl_xor_sync(0xffffffffu, acc, off);
        if (lane == 0) out[b*4 + w] = acc + lb[w];
    }
}

// ---------------- launcher ----------------
extern "C" void kernel_launch(void* const* d_in, const int* in_sizes, int n_in,
                              void* d_out, int out_size) {
    const float* x   = (const float*)d_in[0];
    const float* w1  = (const float*)d_in[1];
    const float* b1  = (const float*)d_in[2];
    const float* g1  = (const float*)d_in[3];
    const float* be1 = (const float*)d_in[4];
    const float* w2  = (const float*)d_in[5];
    const float* b2  = (const float*)d_in[6];
    const float* g2  = (const float*)d_in[7];
    const float* Wq  = (const float*)d_in[9];
    const float* Wk  = (const float*)d_in[10];
    const float* Wv  = (const float*)d_in[11];
    const float* lw  = (const float*)d_in[12];
    const float* lb  = (const float*)d_in[13];

    size_t smem13 = (size_t)(C1*TPAD + C2*C1*12) * sizeof(float);
    cudaFuncSetAttribute(k13, cudaFuncAttributeMaxDynamicSharedMemorySize, (int)smem13);
    cudaFuncSetAttribute(k45, cudaFuncAttributeMaxDynamicSharedMemorySize, SMEM_BYTES);

    zero_stats<<<1, 320>>>();
    k0<<<B_, 256>>>(x);
    kw<<<1, 256>>>(w1, b1, g1, be1, w2, b2);
    k13<<<B_, 256, smem13>>>(x);
    k45<<<B_, 288, SMEM_BYTES>>>(g2, Wq, Wk, Wv, lw, lb, (float*)d_out);
}